// round 1
// baseline (speedup 1.0000x reference)
#include <cuda_runtime.h>
#include <math.h>

#define TOKENS 4096
#define DMODEL 1024
#define NH     16
#define HD     64
#define SEQ    2048

// Scratch (allocation-free): Q/K/V in [b*H+h][s][64] layout, att in [token][H*64]
__device__ float g_q[TOKENS * DMODEL];
__device__ float g_k[TOKENS * DMODEL];
__device__ float g_v[TOKENS * DMODEL];
__device__ float g_att[TOKENS * DMODEL];

// ---------------------------------------------------------------------------
// SGEMM: C = A(M=4096 x K=1024) * B(K=1024 x N=1024)
// 128x128 block tile, BK=8, 256 threads, 8x8 per-thread micro-tile.
// MODE 0: epilogue permutes cols (h,d) / rows (b,s) into [bh][s][d] layout.
// MODE 1: plain row-major + bias.
// ---------------------------------------------------------------------------
template <int MODE>
__global__ __launch_bounds__(256)
void gemm128(const float* __restrict__ A, const float* __restrict__ B,
             float* __restrict__ C, const float* __restrict__ bias)
{
    __shared__ float As[8][128];
    __shared__ float Bs[8][128];

    const int tid = threadIdx.x;
    const int tx  = tid & 15;        // 0..15 -> 8 output cols each
    const int ty  = tid >> 4;        // 0..15 -> 8 output rows each
    const int mBase = blockIdx.y * 128;
    const int nBase = blockIdx.x * 128;

    const int arow = tid >> 1;          // 0..127
    const int acol = (tid & 1) * 4;     // 0 or 4
    const int brow = tid >> 5;          // 0..7
    const int bcol = (tid & 31) * 4;    // 0..124

    float acc[8][8];
    #pragma unroll
    for (int i = 0; i < 8; i++)
        #pragma unroll
        for (int j = 0; j < 8; j++) acc[i][j] = 0.f;

    for (int k0 = 0; k0 < 1024; k0 += 8) {
        float4 av = *(const float4*)&A[(size_t)(mBase + arow) * 1024 + k0 + acol];
        float4 bv = *(const float4*)&B[(size_t)(k0 + brow) * 1024 + nBase + bcol];
        As[acol + 0][arow] = av.x;
        As[acol + 1][arow] = av.y;
        As[acol + 2][arow] = av.z;
        As[acol + 3][arow] = av.w;
        *(float4*)&Bs[brow][bcol] = bv;
        __syncthreads();

        #pragma unroll
        for (int kk = 0; kk < 8; kk++) {
            float a[8], b[8];
            #pragma unroll
            for (int i = 0; i < 8; i++) a[i] = As[kk][ty * 8 + i];
            #pragma unroll
            for (int j = 0; j < 8; j++) b[j] = Bs[kk][tx * 8 + j];
            #pragma unroll
            for (int i = 0; i < 8; i++)
                #pragma unroll
                for (int j = 0; j < 8; j++)
                    acc[i][j] += a[i] * b[j];
        }
        __syncthreads();
    }

    #pragma unroll
    for (int i = 0; i < 8; i++) {
        const int row = mBase + ty * 8 + i;
        const int colBase = nBase + tx * 8;   // 8 contiguous cols, never crosses a 64 boundary
        if (MODE == 0) {
            const int b = row >> 11;          // /2048
            const int s = row & 2047;
            const int h = colBase >> 6;
            const int d = colBase & 63;
            float* dst = &C[(((size_t)(b * NH + h)) * SEQ + s) * HD + d];
            float4 v0 = make_float4(acc[i][0], acc[i][1], acc[i][2], acc[i][3]);
            float4 v1 = make_float4(acc[i][4], acc[i][5], acc[i][6], acc[i][7]);
            *(float4*)&dst[0] = v0;
            *(float4*)&dst[4] = v1;
        } else {
            float* dst = &C[(size_t)row * 1024 + colBase];
            float4 v0 = make_float4(acc[i][0] + bias[colBase + 0],
                                    acc[i][1] + bias[colBase + 1],
                                    acc[i][2] + bias[colBase + 2],
                                    acc[i][3] + bias[colBase + 3]);
            float4 v1 = make_float4(acc[i][4] + bias[colBase + 4],
                                    acc[i][5] + bias[colBase + 5],
                                    acc[i][6] + bias[colBase + 6],
                                    acc[i][7] + bias[colBase + 7]);
            *(float4*)&dst[0] = v0;
            *(float4*)&dst[4] = v1;
        }
    }
}

// ---------------------------------------------------------------------------
// Flash attention, fp32. Grid: (S/64 q-tiles, B*H). 256 threads.
// Per block: 64 q-rows, loop over 64 k-tiles of 32 rows.
// Thread map: 2 q-rows x 4 score-cols (scores) / 2 q-rows x 8 d-cols (output).
// ---------------------------------------------------------------------------
__global__ __launch_bounds__(256)
void flash_kernel(const float* __restrict__ Q, const float* __restrict__ K,
                  const float* __restrict__ V, float* __restrict__ O)
{
    __shared__ float Qs[64][65];     // padded: conflict-free row reads
    __shared__ float Ks[32][65];
    __shared__ float Vs[32][64];
    __shared__ float Ss[64][33];     // padded: conflict-free softmax rows
    __shared__ float alpha_s[64];
    __shared__ float l_s[64];

    const int tid = threadIdx.x;
    const int bh  = blockIdx.y;
    const int qt  = blockIdx.x;

    const float* Qb = Q + (size_t)bh * SEQ * HD + (size_t)qt * 64 * HD;
    const float* Kb = K + (size_t)bh * SEQ * HD;
    const float* Vb = V + (size_t)bh * SEQ * HD;

    // Load + pre-scale Q tile (1/sqrt(64) = 0.125)
    for (int idx = tid; idx < 64 * 64; idx += 256)
        Qs[idx >> 6][idx & 63] = Qb[idx] * 0.125f;

    const int r0 = (tid >> 3) * 2;   // 2 rows
    const int c0 = (tid & 7) * 4;    // 4 score cols
    const int d0 = (tid & 7) * 8;    // 8 output cols

    float accO[2][8];
    #pragma unroll
    for (int i = 0; i < 2; i++)
        #pragma unroll
        for (int j = 0; j < 8; j++) accO[i][j] = 0.f;

    float m_run = -INFINITY, l_run = 0.f;   // live only in tid<64

    for (int kt = 0; kt < SEQ / 32; kt++) {
        __syncthreads();  // previous iter's readers of Ks/Vs/Ss done
        for (int idx = tid; idx < 32 * 64; idx += 256) {
            const int rr = idx >> 6, dd = idx & 63;
            Ks[rr][dd] = Kb[(size_t)(kt * 32 + rr) * HD + dd];
            Vs[rr][dd] = Vb[(size_t)(kt * 32 + rr) * HD + dd];
        }
        __syncthreads();

        // S = Q K^T (64x32 tile)
        float s[2][4];
        #pragma unroll
        for (int i = 0; i < 2; i++)
            #pragma unroll
            for (int j = 0; j < 4; j++) s[i][j] = 0.f;

        #pragma unroll 16
        for (int d = 0; d < HD; d++) {
            const float q0 = Qs[r0][d];
            const float q1 = Qs[r0 + 1][d];
            #pragma unroll
            for (int j = 0; j < 4; j++) {
                const float kv = Ks[c0 + j][d];
                s[0][j] += q0 * kv;
                s[1][j] += q1 * kv;
            }
        }
        #pragma unroll
        for (int i = 0; i < 2; i++)
            #pragma unroll
            for (int j = 0; j < 4; j++)
                Ss[r0 + i][c0 + j] = s[i][j];
        __syncthreads();

        // Online softmax: one thread per q-row
        if (tid < 64) {
            float mt = -INFINITY;
            #pragma unroll
            for (int j = 0; j < 32; j++) mt = fmaxf(mt, Ss[tid][j]);
            const float m_new = fmaxf(m_run, mt);
            const float al = __expf(m_run - m_new);
            float sum = 0.f;
            #pragma unroll
            for (int j = 0; j < 32; j++) {
                const float p = __expf(Ss[tid][j] - m_new);
                Ss[tid][j] = p;
                sum += p;
            }
            l_run = l_run * al + sum;
            m_run = m_new;
            alpha_s[tid] = al;
        }
        __syncthreads();

        // O = O*alpha + P V
        const float a0 = alpha_s[r0];
        const float a1 = alpha_s[r0 + 1];
        #pragma unroll
        for (int j = 0; j < 8; j++) { accO[0][j] *= a0; accO[1][j] *= a1; }

        #pragma unroll 8
        for (int kk = 0; kk < 32; kk++) {
            const float p0 = Ss[r0][kk];
            const float p1 = Ss[r0 + 1][kk];
            #pragma unroll
            for (int j = 0; j < 8; j++) {
                const float vv = Vs[kk][d0 + j];
                accO[0][j] += p0 * vv;
                accO[1][j] += p1 * vv;
            }
        }
    }

    __syncthreads();
    if (tid < 64) l_s[tid] = l_run;
    __syncthreads();

    const int b = bh >> 4, h = bh & 15;
    #pragma unroll
    for (int i = 0; i < 2; i++) {
        const int r = r0 + i;
        const float inv = 1.0f / l_s[r];
        const int token = b * SEQ + qt * 64 + r;
        float* dst = &O[(size_t)token * DMODEL + h * HD + d0];
        #pragma unroll
        for (int j = 0; j < 8; j++) dst[j] = accO[i][j] * inv;
    }
}

// ---------------------------------------------------------------------------
extern "C" void kernel_launch(void* const* d_in, const int* in_sizes, int n_in,
                              void* d_out, int out_size)
{
    const float* x  = (const float*)d_in[0];
    const float* Wq = (const float*)d_in[1];
    const float* Wk = (const float*)d_in[2];
    const float* Wv = (const float*)d_in[3];
    const float* Wo = (const float*)d_in[4];
    const float* bo = (const float*)d_in[5];
    float* out = (float*)d_out;

    float *q, *k, *v, *att;
    cudaGetSymbolAddress((void**)&q,   g_q);
    cudaGetSymbolAddress((void**)&k,   g_k);
    cudaGetSymbolAddress((void**)&v,   g_v);
    cudaGetSymbolAddress((void**)&att, g_att);

    dim3 gGrid(DMODEL / 128, TOKENS / 128);   // (8, 32)
    gemm128<0><<<gGrid, 256>>>(x, Wq, q, nullptr);
    gemm128<0><<<gGrid, 256>>>(x, Wk, k, nullptr);
    gemm128<0><<<gGrid, 256>>>(x, Wv, v, nullptr);

    dim3 fGrid(SEQ / 64, 2 * NH);             // (32, 32)
    flash_kernel<<<fGrid, 256>>>(q, k, v, att);

    gemm128<1><<<gGrid, 256>>>(att, Wo, out, bo);
}

// round 2
// speedup vs baseline: 3.4973x; 3.4973x over previous
#include <cuda_runtime.h>
#include <math.h>
#include <stdint.h>

#define TOKENS 4096
#define DMODEL 1024
#define NH     16
#define HD     64
#define SEQ    2048

// Scratch (allocation-free)
__device__ float g_q[TOKENS * DMODEL];
__device__ float g_k[TOKENS * DMODEL];
__device__ float g_v[TOKENS * DMODEL];
__device__ float g_att[TOKENS * DMODEL];

// ---------------------------------------------------------------------------
// helpers
// ---------------------------------------------------------------------------
__device__ __forceinline__ float to_tf32(float x) {
    uint32_t u;
    asm("cvt.rna.tf32.f32 %0, %1;" : "=r"(u) : "f"(x));
    return __uint_as_float(u);
}

__device__ __forceinline__ void mma_tf32(float* d, const uint32_t* a,
                                         uint32_t b0, uint32_t b1) {
    asm volatile(
        "mma.sync.aligned.m16n8k8.row.col.f32.tf32.tf32.f32 "
        "{%0,%1,%2,%3}, {%4,%5,%6,%7}, {%8,%9}, {%0,%1,%2,%3};\n"
        : "+f"(d[0]), "+f"(d[1]), "+f"(d[2]), "+f"(d[3])
        : "r"(a[0]), "r"(a[1]), "r"(a[2]), "r"(a[3]), "r"(b0), "r"(b1));
}

// ---------------------------------------------------------------------------
// tf32 tensor-core GEMM: C = A(4096x1024) * B(1024x1024)
// Block 128x128, BK=16, 8 warps, warp tile 64x32 (4 m-tiles x 4 n-tiles).
// MODE 0: epilogue scatters into [b*H+h][s][64]; MODE 1: row-major + bias.
// ---------------------------------------------------------------------------
template <int MODE>
__global__ __launch_bounds__(256)
void gemm_tc(const float* __restrict__ A, const float* __restrict__ Bm,
             float* __restrict__ C, const float* __restrict__ bias)
{
    __shared__ float As[128][20];   // [m][k], pad 20: frag banks (20g+c) bijective
    __shared__ float Bs[16][136];   // [k][n], pad 136: frag banks (8c+g) bijective

    const int tid  = threadIdx.x;
    const int lane = tid & 31;
    const int warp = tid >> 5;
    const int g = lane >> 2, c = lane & 3;
    const int mW = (warp & 1) * 64;
    const int nW = (warp >> 1) * 32;
    const int mBase = blockIdx.y * 128;
    const int nBase = blockIdx.x * 128;

    float acc[4][4][4] = {};

    for (int k0 = 0; k0 < 1024; k0 += 16) {
        #pragma unroll
        for (int i = 0; i < 2; i++) {
            int idx = tid + i * 256;          // 512 float4 for each tile
            int m = idx >> 2, kq = idx & 3;
            float4 v = *(const float4*)&A[(size_t)(mBase + m) * 1024 + k0 + kq * 4];
            v.x = to_tf32(v.x); v.y = to_tf32(v.y); v.z = to_tf32(v.z); v.w = to_tf32(v.w);
            *(float4*)&As[m][kq * 4] = v;

            int kB = idx >> 5, nq = idx & 31;
            float4 w = *(const float4*)&Bm[(size_t)(k0 + kB) * 1024 + nBase + nq * 4];
            w.x = to_tf32(w.x); w.y = to_tf32(w.y); w.z = to_tf32(w.z); w.w = to_tf32(w.w);
            *(float4*)&Bs[kB][nq * 4] = w;
        }
        __syncthreads();

        #pragma unroll
        for (int ks = 0; ks < 2; ks++) {
            const int kb = ks * 8;
            uint32_t af[4][4];
            #pragma unroll
            for (int mt = 0; mt < 4; mt++) {
                const int r = mW + mt * 16 + g;
                af[mt][0] = __float_as_uint(As[r][kb + c]);
                af[mt][1] = __float_as_uint(As[r + 8][kb + c]);
                af[mt][2] = __float_as_uint(As[r][kb + c + 4]);
                af[mt][3] = __float_as_uint(As[r + 8][kb + c + 4]);
            }
            uint32_t bf[4][2];
            #pragma unroll
            for (int nt = 0; nt < 4; nt++) {
                const int n = nW + nt * 8 + g;
                bf[nt][0] = __float_as_uint(Bs[kb + c][n]);
                bf[nt][1] = __float_as_uint(Bs[kb + c + 4][n]);
            }
            #pragma unroll
            for (int mt = 0; mt < 4; mt++)
                #pragma unroll
                for (int nt = 0; nt < 4; nt++)
                    mma_tf32(acc[mt][nt], af[mt], bf[nt][0], bf[nt][1]);
        }
        __syncthreads();
    }

    #pragma unroll
    for (int mt = 0; mt < 4; mt++) {
        #pragma unroll
        for (int nt = 0; nt < 4; nt++) {
            const int row = mBase + mW + mt * 16 + g;
            const int col = nBase + nW + nt * 8 + 2 * c;
            if (MODE == 0) {
                const int b = row >> 11, s = row & 2047;
                const int h = col >> 6, d = col & 63;
                float* dst0 = &C[(((size_t)(b * NH + h)) * SEQ + s) * HD + d];
                float* dst1 = &C[(((size_t)(b * NH + h)) * SEQ + s + 8) * HD + d];
                *(float2*)dst0 = make_float2(acc[mt][nt][0], acc[mt][nt][1]);
                *(float2*)dst1 = make_float2(acc[mt][nt][2], acc[mt][nt][3]);
            } else {
                const float b0 = bias[col], b1 = bias[col + 1];
                *(float2*)&C[(size_t)row * 1024 + col] =
                    make_float2(acc[mt][nt][0] + b0, acc[mt][nt][1] + b1);
                *(float2*)&C[(size_t)(row + 8) * 1024 + col] =
                    make_float2(acc[mt][nt][2] + b0, acc[mt][nt][3] + b1);
            }
        }
    }
}

// ---------------------------------------------------------------------------
// Flash attention on tensor cores (tf32 mma), Br=Bc=64.
// 256 threads = 8 warps: warp = (wm 0..3 over 16 q-rows, wn 0..1 over 32 cols).
// Q fragments register-resident; K in natural [s][d] layout (col-major B);
// V transposed in smem; softmax via smem round-trip of S.
// ---------------------------------------------------------------------------
__global__ __launch_bounds__(256)
void flash_tc(const float* __restrict__ Q, const float* __restrict__ K,
              const float* __restrict__ V, float* __restrict__ O)
{
    __shared__ float R2[64][68];    // Q stage -> K tile -> S/P tile (reused)
    __shared__ float Vt[64][67];    // V transposed: [d][kk]
    __shared__ float alpha_s[64];
    __shared__ float l_s[64];

    const int tid  = threadIdx.x;
    const int lane = tid & 31, warp = tid >> 5;
    const int g = lane >> 2, c = lane & 3;
    const int mB = (warp & 3) * 16;
    const int wn = warp >> 2;                 // 0..1
    const int bh = blockIdx.y, qt = blockIdx.x;

    const float* Qb = Q + (size_t)bh * SEQ * HD + (size_t)qt * 64 * HD;
    const float* Kb = K + (size_t)bh * SEQ * HD;
    const float* Vb = V + (size_t)bh * SEQ * HD;

    // Stage Q (pre-scaled by 1/8) into R2, then lift A-fragments to registers.
    #pragma unroll
    for (int i = 0; i < 4; i++) {
        int idx = tid + i * 256;              // 1024 float4
        int dq = idx & 15, m = idx >> 4;
        float4 v = *(const float4*)&Qb[(size_t)m * HD + dq * 4];
        v.x = to_tf32(v.x * 0.125f); v.y = to_tf32(v.y * 0.125f);
        v.z = to_tf32(v.z * 0.125f); v.w = to_tf32(v.w * 0.125f);
        *(float4*)&R2[m][dq * 4] = v;
    }
    __syncthreads();
    uint32_t qf[8][4];
    #pragma unroll
    for (int ks = 0; ks < 8; ks++) {
        const int kb = ks * 8;
        qf[ks][0] = __float_as_uint(R2[mB + g][kb + c]);
        qf[ks][1] = __float_as_uint(R2[mB + g + 8][kb + c]);
        qf[ks][2] = __float_as_uint(R2[mB + g][kb + c + 4]);
        qf[ks][3] = __float_as_uint(R2[mB + g + 8][kb + c + 4]);
    }

    float of[4][4] = {};
    float m_run = -INFINITY, l_run = 0.f;
    const int srow = tid >> 2, sq = tid & 3;

    for (int kt = 0; kt < SEQ / 64; kt++) {
        __syncthreads();   // prior consumers of R2 / Vt are done
        const float* Kt_ = Kb + (size_t)kt * 64 * HD;
        const float* Vp  = Vb + (size_t)kt * 64 * HD;
        #pragma unroll
        for (int i = 0; i < 4; i++) {
            int idx = tid + i * 256;
            int dq = idx & 15, r = idx >> 4;
            float4 kv = *(const float4*)&Kt_[(size_t)r * HD + dq * 4];
            kv.x = to_tf32(kv.x); kv.y = to_tf32(kv.y);
            kv.z = to_tf32(kv.z); kv.w = to_tf32(kv.w);
            *(float4*)&R2[r][dq * 4] = kv;
            float4 vv = *(const float4*)&Vp[(size_t)r * HD + dq * 4];
            Vt[dq * 4 + 0][r] = to_tf32(vv.x);
            Vt[dq * 4 + 1][r] = to_tf32(vv.y);
            Vt[dq * 4 + 2][r] = to_tf32(vv.z);
            Vt[dq * 4 + 3][r] = to_tf32(vv.w);
        }
        __syncthreads();

        // S = Q K^T  (K natural [s][d] == col-major B operand)
        float sf[4][4] = {};
        #pragma unroll
        for (int ks = 0; ks < 8; ks++) {
            const int kb = ks * 8;
            #pragma unroll
            for (int nt = 0; nt < 4; nt++) {
                const int nb = wn * 32 + nt * 8 + g;
                const uint32_t b0 = __float_as_uint(R2[nb][kb + c]);
                const uint32_t b1 = __float_as_uint(R2[nb][kb + c + 4]);
                mma_tf32(sf[nt], qf[ks], b0, b1);
            }
        }
        __syncthreads();   // all K reads complete before S overwrites R2

        #pragma unroll
        for (int nt = 0; nt < 4; nt++) {
            const int colb = wn * 32 + nt * 8 + 2 * c;
            *(float2*)&R2[mB + g][colb]     = make_float2(sf[nt][0], sf[nt][1]);
            *(float2*)&R2[mB + g + 8][colb] = make_float2(sf[nt][2], sf[nt][3]);
        }
        __syncthreads();

        // Online softmax: 4 threads per row, 16 cols each.
        {
            float4 s4[4];
            #pragma unroll
            for (int j = 0; j < 4; j++)
                s4[j] = *(float4*)&R2[srow][sq * 16 + j * 4];
            float mloc = -INFINITY;
            #pragma unroll
            for (int j = 0; j < 4; j++) {
                mloc = fmaxf(mloc, fmaxf(fmaxf(s4[j].x, s4[j].y), fmaxf(s4[j].z, s4[j].w)));
            }
            mloc = fmaxf(mloc, __shfl_xor_sync(0xffffffffu, mloc, 1));
            mloc = fmaxf(mloc, __shfl_xor_sync(0xffffffffu, mloc, 2));
            const float m_new = fmaxf(m_run, mloc);
            const float al = __expf(m_run - m_new);
            float sum = 0.f;
            #pragma unroll
            for (int j = 0; j < 4; j++) {
                s4[j].x = __expf(s4[j].x - m_new); sum += s4[j].x;
                s4[j].y = __expf(s4[j].y - m_new); sum += s4[j].y;
                s4[j].z = __expf(s4[j].z - m_new); sum += s4[j].z;
                s4[j].w = __expf(s4[j].w - m_new); sum += s4[j].w;
                s4[j].x = to_tf32(s4[j].x); s4[j].y = to_tf32(s4[j].y);
                s4[j].z = to_tf32(s4[j].z); s4[j].w = to_tf32(s4[j].w);
                *(float4*)&R2[srow][sq * 16 + j * 4] = s4[j];
            }
            sum += __shfl_xor_sync(0xffffffffu, sum, 1);
            sum += __shfl_xor_sync(0xffffffffu, sum, 2);
            l_run = l_run * al + sum;
            m_run = m_new;
            if (sq == 0) alpha_s[srow] = al;
        }
        __syncthreads();

        // O = O*alpha + P V
        {
            const float a0 = alpha_s[mB + g], a1 = alpha_s[mB + g + 8];
            #pragma unroll
            for (int nt = 0; nt < 4; nt++) {
                of[nt][0] *= a0; of[nt][1] *= a0;
                of[nt][2] *= a1; of[nt][3] *= a1;
            }
        }
        #pragma unroll
        for (int ks = 0; ks < 8; ks++) {
            const int kb = ks * 8;
            uint32_t pa[4];
            pa[0] = __float_as_uint(R2[mB + g][kb + c]);
            pa[1] = __float_as_uint(R2[mB + g + 8][kb + c]);
            pa[2] = __float_as_uint(R2[mB + g][kb + c + 4]);
            pa[3] = __float_as_uint(R2[mB + g + 8][kb + c + 4]);
            #pragma unroll
            for (int nt = 0; nt < 4; nt++) {
                const int nb = wn * 32 + nt * 8 + g;
                const uint32_t b0 = __float_as_uint(Vt[nb][kb + c]);
                const uint32_t b1 = __float_as_uint(Vt[nb][kb + c + 4]);
                mma_tf32(of[nt], pa, b0, b1);
            }
        }
    }

    __syncthreads();
    if (sq == 0) l_s[srow] = l_run;
    __syncthreads();

    const float inv0 = 1.f / l_s[mB + g];
    const float inv1 = 1.f / l_s[mB + g + 8];
    const int b = bh >> 4, h = bh & 15;
    #pragma unroll
    for (int nt = 0; nt < 4; nt++) {
        const int col = wn * 32 + nt * 8 + 2 * c;
        const int token0 = b * SEQ + qt * 64 + mB + g;
        *(float2*)&O[(size_t)token0 * DMODEL + h * HD + col] =
            make_float2(of[nt][0] * inv0, of[nt][1] * inv0);
        *(float2*)&O[(size_t)(token0 + 8) * DMODEL + h * HD + col] =
            make_float2(of[nt][2] * inv1, of[nt][3] * inv1);
    }
}

// ---------------------------------------------------------------------------
extern "C" void kernel_launch(void* const* d_in, const int* in_sizes, int n_in,
                              void* d_out, int out_size)
{
    const float* x  = (const float*)d_in[0];
    const float* Wq = (const float*)d_in[1];
    const float* Wk = (const float*)d_in[2];
    const float* Wv = (const float*)d_in[3];
    const float* Wo = (const float*)d_in[4];
    const float* bo = (const float*)d_in[5];
    float* out = (float*)d_out;

    float *q, *k, *v, *att;
    cudaGetSymbolAddress((void**)&q,   g_q);
    cudaGetSymbolAddress((void**)&k,   g_k);
    cudaGetSymbolAddress((void**)&v,   g_v);
    cudaGetSymbolAddress((void**)&att, g_att);

    dim3 gGrid(DMODEL / 128, TOKENS / 128);   // (8, 32)
    gemm_tc<0><<<gGrid, 256>>>(x, Wq, q, nullptr);
    gemm_tc<0><<<gGrid, 256>>>(x, Wk, k, nullptr);
    gemm_tc<0><<<gGrid, 256>>>(x, Wv, v, nullptr);

    dim3 fGrid(SEQ / 64, 2 * NH);             // (32, 32)
    flash_tc<<<fGrid, 256>>>(q, k, v, att);

    gemm_tc<1><<<gGrid, 256>>>(att, Wo, out, bo);
}

// round 3
// speedup vs baseline: 4.3302x; 1.2382x over previous
#include <cuda_runtime.h>
#include <math.h>
#include <stdint.h>

#define TOKENS 4096
#define DMODEL 1024
#define NH     16
#define HD     64
#define SEQ    2048

// Scratch (allocation-free)
__device__ float g_q[TOKENS * DMODEL];
__device__ float g_k[TOKENS * DMODEL];
__device__ float g_v[TOKENS * DMODEL];
__device__ float g_att[TOKENS * DMODEL];

// ---------------------------------------------------------------------------
// helpers
// ---------------------------------------------------------------------------
__device__ __forceinline__ float to_tf32(float x) {
    uint32_t u;
    asm("cvt.rna.tf32.f32 %0, %1;" : "=r"(u) : "f"(x));
    return __uint_as_float(u);
}

__device__ __forceinline__ void mma_tf32(float* d, const uint32_t* a,
                                         uint32_t b0, uint32_t b1) {
    asm volatile(
        "mma.sync.aligned.m16n8k8.row.col.f32.tf32.tf32.f32 "
        "{%0,%1,%2,%3}, {%4,%5,%6,%7}, {%8,%9}, {%0,%1,%2,%3};\n"
        : "+f"(d[0]), "+f"(d[1]), "+f"(d[2]), "+f"(d[3])
        : "r"(a[0]), "r"(a[1]), "r"(a[2]), "r"(a[3]), "r"(b0), "r"(b1));
}

__device__ __forceinline__ void ldsm4(uint32_t& r0, uint32_t& r1,
                                      uint32_t& r2, uint32_t& r3,
                                      const float* p) {
    uint32_t addr = (uint32_t)__cvta_generic_to_shared(p);
    asm volatile("ldmatrix.sync.aligned.m8n8.x4.shared.b16 {%0,%1,%2,%3}, [%4];"
                 : "=r"(r0), "=r"(r1), "=r"(r2), "=r"(r3) : "r"(addr));
}

// ---------------------------------------------------------------------------
// tf32 tensor-core GEMM (unchanged from R2): C = A(4096x1024)*B(1024x1024)
// ---------------------------------------------------------------------------
template <int MODE>
__global__ __launch_bounds__(256)
void gemm_tc(const float* __restrict__ A, const float* __restrict__ Bm,
             float* __restrict__ C, const float* __restrict__ bias)
{
    __shared__ float As[128][20];
    __shared__ float Bs[16][136];

    const int tid  = threadIdx.x;
    const int lane = tid & 31;
    const int warp = tid >> 5;
    const int g = lane >> 2, c = lane & 3;
    const int mW = (warp & 1) * 64;
    const int nW = (warp >> 1) * 32;
    const int mBase = blockIdx.y * 128;
    const int nBase = blockIdx.x * 128;

    float acc[4][4][4] = {};

    for (int k0 = 0; k0 < 1024; k0 += 16) {
        #pragma unroll
        for (int i = 0; i < 2; i++) {
            int idx = tid + i * 256;
            int m = idx >> 2, kq = idx & 3;
            float4 v = *(const float4*)&A[(size_t)(mBase + m) * 1024 + k0 + kq * 4];
            v.x = to_tf32(v.x); v.y = to_tf32(v.y); v.z = to_tf32(v.z); v.w = to_tf32(v.w);
            *(float4*)&As[m][kq * 4] = v;

            int kB = idx >> 5, nq = idx & 31;
            float4 w = *(const float4*)&Bm[(size_t)(k0 + kB) * 1024 + nBase + nq * 4];
            w.x = to_tf32(w.x); w.y = to_tf32(w.y); w.z = to_tf32(w.z); w.w = to_tf32(w.w);
            *(float4*)&Bs[kB][nq * 4] = w;
        }
        __syncthreads();

        #pragma unroll
        for (int ks = 0; ks < 2; ks++) {
            const int kb = ks * 8;
            uint32_t af[4][4];
            #pragma unroll
            for (int mt = 0; mt < 4; mt++) {
                const int r = mW + mt * 16 + g;
                af[mt][0] = __float_as_uint(As[r][kb + c]);
                af[mt][1] = __float_as_uint(As[r + 8][kb + c]);
                af[mt][2] = __float_as_uint(As[r][kb + c + 4]);
                af[mt][3] = __float_as_uint(As[r + 8][kb + c + 4]);
            }
            uint32_t bf[4][2];
            #pragma unroll
            for (int nt = 0; nt < 4; nt++) {
                const int n = nW + nt * 8 + g;
                bf[nt][0] = __float_as_uint(Bs[kb + c][n]);
                bf[nt][1] = __float_as_uint(Bs[kb + c + 4][n]);
            }
            #pragma unroll
            for (int mt = 0; mt < 4; mt++)
                #pragma unroll
                for (int nt = 0; nt < 4; nt++)
                    mma_tf32(acc[mt][nt], af[mt], bf[nt][0], bf[nt][1]);
        }
        __syncthreads();
    }

    #pragma unroll
    for (int mt = 0; mt < 4; mt++) {
        #pragma unroll
        for (int nt = 0; nt < 4; nt++) {
            const int row = mBase + mW + mt * 16 + g;
            const int col = nBase + nW + nt * 8 + 2 * c;
            if (MODE == 0) {
                const int b = row >> 11, s = row & 2047;
                const int h = col >> 6, d = col & 63;
                float* dst0 = &C[(((size_t)(b * NH + h)) * SEQ + s) * HD + d];
                float* dst1 = &C[(((size_t)(b * NH + h)) * SEQ + s + 8) * HD + d];
                *(float2*)dst0 = make_float2(acc[mt][nt][0], acc[mt][nt][1]);
                *(float2*)dst1 = make_float2(acc[mt][nt][2], acc[mt][nt][3]);
            } else {
                const float b0 = bias[col], b1 = bias[col + 1];
                *(float2*)&C[(size_t)row * 1024 + col] =
                    make_float2(acc[mt][nt][0] + b0, acc[mt][nt][1] + b1);
                *(float2*)&C[(size_t)(row + 8) * 1024 + col] =
                    make_float2(acc[mt][nt][2] + b0, acc[mt][nt][3] + b1);
            }
        }
    }
}

// ---------------------------------------------------------------------------
// Flash attention v2: ldmatrix everywhere, in-register softmax.
// Br=128 (8 warps x 16 rows), Bc=64. Each warp: 16 q-rows x all 64 k-cols.
// Dynamic smem: Ks[64][68] | Vt[64][68] | Pw[8][16][68]
// ---------------------------------------------------------------------------
__global__ __launch_bounds__(256, 2)
void flash_tc2(const float* __restrict__ Q, const float* __restrict__ K,
               const float* __restrict__ V, float* __restrict__ O)
{
    extern __shared__ float smem[];
    float* Ks = smem;                      // [64][68]
    float* Vt = smem + 64 * 68;            // [64][68]  (Vt[d][token])
    const int tid  = threadIdx.x;
    const int lane = tid & 31, warp = tid >> 5;
    float* Pw = smem + 2 * 64 * 68 + warp * 16 * 68;   // [16][68] per warp

    const int g  = lane >> 2, c = lane & 3;
    const int lr = lane & 7;
    const int mB = warp * 16;
    const int bh = blockIdx.y, qt = blockIdx.x;

    const float* Qw = Q + (size_t)bh * SEQ * HD + (size_t)(qt * 128 + mB) * HD;
    const float* Kb = K + (size_t)bh * SEQ * HD;
    const float* Vb = V + (size_t)bh * SEQ * HD;

    // ldmatrix lane-address components
    const int aRow = lr + ((lane & 8) ? 8 : 0);      // A-frag row
    const int aCol = (lane & 16) ? 4 : 0;            // A-frag col half
    const int bColH = (lane & 8) ? 4 : 0;            // B-frag col half
    const int bNtH  = (lane & 16) ? 1 : 0;           // B-frag tile-within-pair

    // ---- stage Q (scaled, tf32) into Pw, lift A-fragments ----
    #pragma unroll
    for (int i = 0; i < 8; i++) {
        int idx = lane + i * 32;                     // 256 quads: 16 rows x 16
        int r = idx >> 4, dq = idx & 15;
        float4 v = *(const float4*)&Qw[(size_t)r * HD + dq * 4];
        v.x = to_tf32(v.x * 0.125f); v.y = to_tf32(v.y * 0.125f);
        v.z = to_tf32(v.z * 0.125f); v.w = to_tf32(v.w * 0.125f);
        *(float4*)&Pw[r * 68 + dq * 4] = v;
    }
    __syncwarp();
    uint32_t qf[8][4];
    #pragma unroll
    for (int ks = 0; ks < 8; ks++)
        ldsm4(qf[ks][0], qf[ks][1], qf[ks][2], qf[ks][3],
              Pw + aRow * 68 + ks * 8 + aCol);

    float of[8][4] = {};
    float m0 = -INFINITY, m1 = -INFINITY, l0 = 0.f, l1 = 0.f;

    for (int kt = 0; kt < SEQ / 64; kt++) {
        __syncthreads();
        // K tile: natural [token][d], float4 coalesced
        const float* Kt_ = Kb + (size_t)kt * 64 * HD;
        const float* Vp  = Vb + (size_t)kt * 64 * HD;
        #pragma unroll
        for (int i = 0; i < 4; i++) {
            int idx = tid + i * 256;
            int r = idx >> 4, dq = idx & 15;
            float4 kv = *(const float4*)&Kt_[(size_t)r * HD + dq * 4];
            kv.x = to_tf32(kv.x); kv.y = to_tf32(kv.y);
            kv.z = to_tf32(kv.z); kv.w = to_tf32(kv.w);
            *(float4*)&Ks[r * 68 + dq * 4] = kv;
        }
        // V tile transposed: scalar-gather map, STS.128 conflict-free
        {
            const int d = (lane & 7) + 8 * warp;
            #pragma unroll
            for (int i = 0; i < 4; i++) {
                const int tq = (lane >> 3) + 4 * i;
                float4 vv;
                vv.x = to_tf32(Vp[(size_t)(tq * 4 + 0) * HD + d]);
                vv.y = to_tf32(Vp[(size_t)(tq * 4 + 1) * HD + d]);
                vv.z = to_tf32(Vp[(size_t)(tq * 4 + 2) * HD + d]);
                vv.w = to_tf32(Vp[(size_t)(tq * 4 + 3) * HD + d]);
                *(float4*)&Vt[d * 68 + tq * 4] = vv;
            }
        }
        __syncthreads();

        // ---- S = Q K^T (8 n-tiles per warp) ----
        float sf[8][4] = {};
        #pragma unroll
        for (int ks = 0; ks < 8; ks++) {
            const int kb = ks * 8;
            #pragma unroll
            for (int ntp = 0; ntp < 4; ntp++) {
                uint32_t b0, b1, b2, b3;
                const int row = (ntp * 2 + bNtH) * 8 + lr;
                ldsm4(b0, b1, b2, b3, Ks + row * 68 + kb + bColH);
                mma_tf32(sf[ntp * 2],     qf[ks], b0, b1);
                mma_tf32(sf[ntp * 2 + 1], qf[ks], b2, b3);
            }
        }

        // ---- online softmax in registers ----
        float mx0 = -INFINITY, mx1 = -INFINITY;
        #pragma unroll
        for (int nt = 0; nt < 8; nt++) {
            mx0 = fmaxf(mx0, fmaxf(sf[nt][0], sf[nt][1]));
            mx1 = fmaxf(mx1, fmaxf(sf[nt][2], sf[nt][3]));
        }
        mx0 = fmaxf(mx0, __shfl_xor_sync(0xffffffffu, mx0, 1));
        mx0 = fmaxf(mx0, __shfl_xor_sync(0xffffffffu, mx0, 2));
        mx1 = fmaxf(mx1, __shfl_xor_sync(0xffffffffu, mx1, 1));
        mx1 = fmaxf(mx1, __shfl_xor_sync(0xffffffffu, mx1, 2));
        const float mn0 = fmaxf(m0, mx0), mn1 = fmaxf(m1, mx1);
        const float al0 = __expf(m0 - mn0), al1 = __expf(m1 - mn1);
        float s0 = 0.f, s1 = 0.f;
        #pragma unroll
        for (int nt = 0; nt < 8; nt++) {
            sf[nt][0] = __expf(sf[nt][0] - mn0); s0 += sf[nt][0];
            sf[nt][1] = __expf(sf[nt][1] - mn0); s0 += sf[nt][1];
            sf[nt][2] = __expf(sf[nt][2] - mn1); s1 += sf[nt][2];
            sf[nt][3] = __expf(sf[nt][3] - mn1); s1 += sf[nt][3];
        }
        s0 += __shfl_xor_sync(0xffffffffu, s0, 1);
        s0 += __shfl_xor_sync(0xffffffffu, s0, 2);
        s1 += __shfl_xor_sync(0xffffffffu, s1, 1);
        s1 += __shfl_xor_sync(0xffffffffu, s1, 2);
        l0 = l0 * al0 + s0;  m0 = mn0;
        l1 = l1 * al1 + s1;  m1 = mn1;
        #pragma unroll
        for (int nt = 0; nt < 8; nt++) {
            of[nt][0] *= al0; of[nt][1] *= al0;
            of[nt][2] *= al1; of[nt][3] *= al1;
        }

        // ---- P to warp-private smem (tf32), re-lift as A-frag ----
        #pragma unroll
        for (int nt = 0; nt < 8; nt++) {
            *(float2*)&Pw[g * 68 + nt * 8 + 2 * c] =
                make_float2(to_tf32(sf[nt][0]), to_tf32(sf[nt][1]));
            *(float2*)&Pw[(g + 8) * 68 + nt * 8 + 2 * c] =
                make_float2(to_tf32(sf[nt][2]), to_tf32(sf[nt][3]));
        }
        __syncwarp();

        // ---- O += P V ----
        #pragma unroll
        for (int ks = 0; ks < 8; ks++) {
            const int kb = ks * 8;
            uint32_t pf[4];
            ldsm4(pf[0], pf[1], pf[2], pf[3], Pw + aRow * 68 + kb + aCol);
            #pragma unroll
            for (int ntp = 0; ntp < 4; ntp++) {
                uint32_t b0, b1, b2, b3;
                const int row = (ntp * 2 + bNtH) * 8 + lr;
                ldsm4(b0, b1, b2, b3, Vt + row * 68 + kb + bColH);
                mma_tf32(of[ntp * 2],     pf, b0, b1);
                mma_tf32(of[ntp * 2 + 1], pf, b2, b3);
            }
        }
        __syncwarp();   // Pw reads done before next-iter softmax writes
    }

    // ---- epilogue ----
    const float inv0 = 1.f / l0, inv1 = 1.f / l1;
    const int b = bh >> 4, h = bh & 15;
    const int token0 = b * SEQ + qt * 128 + mB + g;
    #pragma unroll
    for (int nt = 0; nt < 8; nt++) {
        const int col = h * HD + nt * 8 + 2 * c;
        *(float2*)&O[(size_t)token0 * DMODEL + col] =
            make_float2(of[nt][0] * inv0, of[nt][1] * inv0);
        *(float2*)&O[(size_t)(token0 + 8) * DMODEL + col] =
            make_float2(of[nt][2] * inv1, of[nt][3] * inv1);
    }
}

// ---------------------------------------------------------------------------
extern "C" void kernel_launch(void* const* d_in, const int* in_sizes, int n_in,
                              void* d_out, int out_size)
{
    const float* x  = (const float*)d_in[0];
    const float* Wq = (const float*)d_in[1];
    const float* Wk = (const float*)d_in[2];
    const float* Wv = (const float*)d_in[3];
    const float* Wo = (const float*)d_in[4];
    const float* bo = (const float*)d_in[5];
    float* out = (float*)d_out;

    float *q, *k, *v, *att;
    cudaGetSymbolAddress((void**)&q,   g_q);
    cudaGetSymbolAddress((void**)&k,   g_k);
    cudaGetSymbolAddress((void**)&v,   g_v);
    cudaGetSymbolAddress((void**)&att, g_att);

    const int FLASH_SMEM = (2 * 64 * 68 + 8 * 16 * 68) * 4;   // 69632 B
    static int smem_set = 0;
    if (!smem_set) {
        cudaFuncSetAttribute(flash_tc2,
            cudaFuncAttributeMaxDynamicSharedMemorySize, FLASH_SMEM);
        smem_set = 1;
    }

    dim3 gGrid(DMODEL / 128, TOKENS / 128);   // (8, 32)
    gemm_tc<0><<<gGrid, 256>>>(x, Wq, q, nullptr);
    gemm_tc<0><<<gGrid, 256>>>(x, Wk, k, nullptr);
    gemm_tc<0><<<gGrid, 256>>>(x, Wv, v, nullptr);

    dim3 fGrid(SEQ / 128, 2 * NH);            // (16, 32)
    flash_tc2<<<fGrid, 256, FLASH_SMEM>>>(q, k, v, att);

    gemm_tc<1><<<gGrid, 256>>>(att, Wo, out, bo);
}